// round 1
// baseline (speedup 1.0000x reference)
#include <cuda_runtime.h>
#include <math.h>

// Problem constants
constexpr int Bv = 128;   // batch
constexpr int Nv = 512;   // nodes
constexpr int Kv = 10;    // neighbors
constexpr int Fv = 128;   // features
constexpr int TFv = 256;  // 2F (cat width)
constexpr int Cv = 40;    // classes

// Layer-kernel tiling
constexpr int ROWS    = 64;    // rows (b,n) per block
constexpr int THREADS = 256;
constexpr int FCH     = 64;    // f-chunk of W staged in shared
constexpr int CATP    = 260;   // padded cat row (bank-conflict-free)
constexpr int WP      = 132;   // padded W row
constexpr int SMEM_BYTES = (ROWS * CATP + FCH * WP) * 4;  // ~98 KB

// Scratch (static device globals: allocation-free rule)
__device__ float g_h1[Bv * Nv * Fv];
__device__ float g_h2[Bv * Nv * Fv];

// Fused: mp = mean_k h[b, neigh[b,n,k], :] ; cat = [mp, h] ; hout = cat @ W^T + bias
__global__ __launch_bounds__(THREADS) void sage_layer_kernel(
    const float* __restrict__ hin, const int* __restrict__ neigh,
    const float* __restrict__ w,   const float* __restrict__ bias,
    float* __restrict__ hout)
{
    extern __shared__ float smem[];
    float (*s_cat)[CATP] = (float (*)[CATP])smem;
    float (*s_w)[WP]     = (float (*)[WP])(smem + ROWS * CATP);

    const int t    = threadIdx.x;
    const int lane = t & 31;
    const int warp = t >> 5;
    const int row0 = blockIdx.x * ROWS;

    // ---- Phase 1: gather-mean + self copy into shared cat tile ----
    // 8 warps x 8 rows; each lane owns one float4 (32 float4 = 128 floats)
    for (int r = warp * 8; r < warp * 8 + 8; ++r) {
        const int rowg = row0 + r;          // = b*N + n
        const int b    = rowg >> 9;         // N = 512
        const int* nb  = neigh + rowg * Kv;
        float4 acc = make_float4(0.f, 0.f, 0.f, 0.f);
        #pragma unroll
        for (int k = 0; k < Kv; ++k) {
            const int idx = __ldg(nb + k);
            const float4 v = __ldg((const float4*)(hin + (b * Nv + idx) * Fv) + lane);
            acc.x += v.x; acc.y += v.y; acc.z += v.z; acc.w += v.w;
        }
        const float inv = 1.0f / Kv;
        acc.x *= inv; acc.y *= inv; acc.z *= inv; acc.w *= inv;
        *(float4*)&s_cat[r][lane * 4] = acc;
        const float4 hv = __ldg((const float4*)(hin + rowg * Fv) + lane);
        *(float4*)&s_cat[r][Fv + lane * 4] = hv;
    }
    __syncthreads();

    // ---- Phase 2: 64x128 GEMM, thread tile 4 rows x 8 cols ----
    const int ty = t >> 4, tx = t & 15;
    const int ty4 = ty * 4, tx8 = tx * 8;

    float acc[4][8];
    #pragma unroll
    for (int i = 0; i < 4; ++i)
        #pragma unroll
        for (int j = 0; j < 8; ++j) acc[i][j] = 0.f;

    for (int fc = 0; fc < TFv; fc += FCH) {
        // stage W chunk transposed: s_w[f][g] = W[g][fc+f]  (coalesced global reads)
        for (int e = t; e < FCH * Fv; e += THREADS) {
            const int f = e & (FCH - 1);
            const int g = e >> 6;
            s_w[f][g] = __ldg(w + g * TFv + fc + f);
        }
        __syncthreads();

        #pragma unroll 8
        for (int f = 0; f < FCH; ++f) {
            const float a0 = s_cat[ty4 + 0][fc + f];
            const float a1 = s_cat[ty4 + 1][fc + f];
            const float a2 = s_cat[ty4 + 2][fc + f];
            const float a3 = s_cat[ty4 + 3][fc + f];
            const float4 w0 = *(const float4*)&s_w[f][tx8];
            const float4 w1 = *(const float4*)&s_w[f][tx8 + 4];
            const float wv[8] = {w0.x, w0.y, w0.z, w0.w, w1.x, w1.y, w1.z, w1.w};
            #pragma unroll
            for (int j = 0; j < 8; ++j) {
                acc[0][j] = fmaf(a0, wv[j], acc[0][j]);
                acc[1][j] = fmaf(a1, wv[j], acc[1][j]);
                acc[2][j] = fmaf(a2, wv[j], acc[2][j]);
                acc[3][j] = fmaf(a3, wv[j], acc[3][j]);
            }
        }
        __syncthreads();
    }

    // ---- Epilogue: + bias, store ----
    float bja[8];
    #pragma unroll
    for (int j = 0; j < 8; ++j) bja[j] = __ldg(bias + tx8 + j);
    #pragma unroll
    for (int i = 0; i < 4; ++i) {
        const int rowg = row0 + ty4 + i;
        float* o = hout + rowg * Fv + tx8;
        float4 o0 = make_float4(acc[i][0] + bja[0], acc[i][1] + bja[1],
                                acc[i][2] + bja[2], acc[i][3] + bja[3]);
        float4 o1 = make_float4(acc[i][4] + bja[4], acc[i][5] + bja[5],
                                acc[i][6] + bja[6], acc[i][7] + bja[7]);
        *(float4*)o = o0;
        *(float4*)(o + 4) = o1;
    }
}

// Tail: out = softmax( relu(BN(h[:,0,:] @ l1w^T + l1b)) @ l2w^T + l2b )
__global__ __launch_bounds__(256) void tail_kernel(
    const float* __restrict__ h,
    const float* __restrict__ l1w, const float* __restrict__ l1b,
    const float* __restrict__ gamma, const float* __restrict__ beta,
    const float* __restrict__ l2w, const float* __restrict__ l2b,
    float* __restrict__ out)
{
    __shared__ float s_z[Bv][65];
    __shared__ float s_scale[64], s_shift[64];
    const int t = threadIdx.x;

    // z = h[:,0,:] @ l1w^T + l1b   (128 x 64)
    for (int o = t; o < Bv * 64; o += 256) {
        const int b = o >> 6, j = o & 63;
        const float* hr = h + b * Nv * Fv;   // row (b, n=0)
        const float* wr = l1w + j * Fv;
        float s = 0.f;
        #pragma unroll 4
        for (int f = 0; f < Fv; ++f) s = fmaf(hr[f], wr[f], s);
        s_z[b][j] = s + l1b[j];
    }
    __syncthreads();

    // batch-norm statistics over the batch dimension (B=128)
    if (t < 64) {
        float mu = 0.f;
        for (int b = 0; b < Bv; ++b) mu += s_z[b][t];
        mu *= (1.0f / Bv);
        float var = 0.f;
        for (int b = 0; b < Bv; ++b) { const float d = s_z[b][t] - mu; var += d * d; }
        var *= (1.0f / Bv);
        const float sc = gamma[t] * rsqrtf(var + 1e-5f);
        s_scale[t] = sc;
        s_shift[t] = beta[t] - mu * sc;
    }
    __syncthreads();

    // normalize + relu in place
    for (int o = t; o < Bv * 64; o += 256) {
        const int b = o >> 6, j = o & 63;
        s_z[b][j] = fmaxf(s_z[b][j] * s_scale[j] + s_shift[j], 0.f);
    }
    __syncthreads();

    // lin2 + softmax, one thread per batch row
    if (t < Bv) {
        float lg[Cv];
        #pragma unroll
        for (int c = 0; c < Cv; ++c) {
            const float* wr = l2w + c * 64;
            float s = 0.f;
            #pragma unroll
            for (int j = 0; j < 64; ++j) s = fmaf(s_z[t][j], wr[j], s);
            lg[c] = s + l2b[c];
        }
        float m = lg[0];
        #pragma unroll
        for (int c = 1; c < Cv; ++c) m = fmaxf(m, lg[c]);
        float sum = 0.f;
        #pragma unroll
        for (int c = 0; c < Cv; ++c) { lg[c] = expf(lg[c] - m); sum += lg[c]; }
        const float r = 1.0f / sum;
        #pragma unroll
        for (int c = 0; c < Cv; ++c) out[t * Cv + c] = lg[c] * r;
    }
}

extern "C" void kernel_launch(void* const* d_in, const int* in_sizes, int n_in,
                              void* d_out, int out_size) {
    const float* x      = (const float*)d_in[0];
    const int*   neigh  = (const int*)  d_in[1];
    const float* w_sage = (const float*)d_in[2];
    const float* b_sage = (const float*)d_in[3];
    const float* l1w    = (const float*)d_in[4];
    const float* l1b    = (const float*)d_in[5];
    const float* gamma  = (const float*)d_in[6];
    const float* beta   = (const float*)d_in[7];
    const float* l2w    = (const float*)d_in[8];
    const float* l2b    = (const float*)d_in[9];
    float* out = (float*)d_out;

    // idempotent; capture-safe (not a stream op)
    cudaFuncSetAttribute(sage_layer_kernel,
                         cudaFuncAttributeMaxDynamicSharedMemorySize, SMEM_BYTES);

    void *p1, *p2;
    cudaGetSymbolAddress(&p1, g_h1);
    cudaGetSymbolAddress(&p2, g_h2);
    float* h1 = (float*)p1;
    float* h2 = (float*)p2;

    const int grid = (Bv * Nv) / ROWS;  // 1024
    // layer 0: x -> h1
    sage_layer_kernel<<<grid, THREADS, SMEM_BYTES>>>(x, neigh, w_sage, b_sage, h1);
    // layer 1: h1 -> h2
    sage_layer_kernel<<<grid, THREADS, SMEM_BYTES>>>(h1, neigh, w_sage + Fv * TFv,
                                                     b_sage + Fv, h2);
    // MLP head
    tail_kernel<<<1, 256>>>(h2, l1w, l1b, gamma, beta, l2w, l2b, out);
}

// round 2
// speedup vs baseline: 2.5689x; 2.5689x over previous
#include <cuda_runtime.h>
#include <math.h>

// Problem constants
constexpr int Bv = 128;   // batch
constexpr int Nv = 512;   // nodes
constexpr int Kv = 10;    // neighbors
constexpr int Fv = 128;   // features
constexpr int TFv = 256;  // 2F (cat width)
constexpr int Cv = 40;    // classes

// Layer-kernel tiling
constexpr int ROWS    = 64;    // rows (b,n) per block
constexpr int THREADS = 256;
constexpr int FCH     = 64;    // f-chunk of W staged in shared
constexpr int CATP    = 260;   // padded cat row (16B-aligned rows, broadcast reads)
constexpr int WP      = 132;   // padded W row (16B-aligned, conflict-free LDS.128)
constexpr int SMEM_BYTES = (ROWS * CATP + FCH * WP) * 4;  // ~100 KB

// Scratch (static device globals: allocation-free rule)
__device__ float g_h1[Bv * Nv * Fv];
__device__ float g_h2[Bv * Nv * Fv];
__device__ float g_wT[2 * TFv * Fv];   // transposed sage weights: [l][f][g]
__device__ float g_z[Bv * 64];         // lin1 output

// ---- packed fp32x2 helpers (Blackwell FFMA2: 2 FMAs per issue, bit-exact fp32) ----
__device__ __forceinline__ unsigned long long pk2(float lo, float hi) {
    unsigned long long r;
    asm("mov.b64 %0, {%1, %2};" : "=l"(r) : "f"(lo), "f"(hi));
    return r;
}
__device__ __forceinline__ void fma2(unsigned long long& c,
                                     unsigned long long a, unsigned long long b) {
    asm("fma.rn.f32x2 %0, %1, %2, %0;" : "+l"(c) : "l"(a), "l"(b));
}
__device__ __forceinline__ void upk2(unsigned long long v, float& lo, float& hi) {
    asm("mov.b64 {%0, %1}, %2;" : "=f"(lo), "=f"(hi) : "l"(v));
}

// One-time per replay: wT[l][f][g] = w[l][g][f]
__global__ __launch_bounds__(256) void transpose_w_kernel(
    const float* __restrict__ w, float* __restrict__ wT)
{
    const int idx = blockIdx.x * 256 + threadIdx.x;   // 2*256*128 = 65536 total
    const int l = idx >> 15;
    const int r = idx & 32767;
    const int f = r >> 7;
    const int g = r & 127;
    wT[idx] = w[l * (TFv * Fv) + g * TFv + f];
}

// Fused: mp = mean_k h[b, neigh[b,n,k], :] ; cat = [mp, h] ; hout = cat @ W^T + bias
__global__ __launch_bounds__(THREADS, 2) void sage_layer_kernel(
    const float* __restrict__ hin, const int* __restrict__ neigh,
    const float* __restrict__ wT,  const float* __restrict__ bias,
    float* __restrict__ hout)
{
    extern __shared__ float smem[];
    float (*s_cat)[CATP] = (float (*)[CATP])smem;
    float (*s_w)[WP]     = (float (*)[WP])(smem + ROWS * CATP);

    const int t    = threadIdx.x;
    const int lane = t & 31;
    const int warp = t >> 5;
    const int row0 = blockIdx.x * ROWS;

    // ---- Phase 1: gather-mean + self copy into shared cat tile ----
    for (int r = warp * 8; r < warp * 8 + 8; ++r) {
        const int rowg = row0 + r;          // = b*N + n
        const int b    = rowg >> 9;         // N = 512
        const int* nb  = neigh + rowg * Kv;
        float4 acc = make_float4(0.f, 0.f, 0.f, 0.f);
        #pragma unroll
        for (int k = 0; k < Kv; ++k) {
            const int idx = __ldg(nb + k);
            const float4 v = __ldg((const float4*)(hin + (b * Nv + idx) * Fv) + lane);
            acc.x += v.x; acc.y += v.y; acc.z += v.z; acc.w += v.w;
        }
        const float inv = 1.0f / Kv;
        acc.x *= inv; acc.y *= inv; acc.z *= inv; acc.w *= inv;
        *(float4*)&s_cat[r][lane * 4] = acc;
        const float4 hv = __ldg((const float4*)(hin + rowg * Fv) + lane);
        *(float4*)&s_cat[r][Fv + lane * 4] = hv;
    }
    __syncthreads();

    // ---- Phase 2: 64x128 GEMM via packed FFMA2, thread tile 4 rows x 8 cols ----
    const int ty = t >> 4, tx = t & 15;
    const int ty4 = ty * 4, tx8 = tx * 8;

    unsigned long long acc2[4][4];
    #pragma unroll
    for (int i = 0; i < 4; ++i)
        #pragma unroll
        for (int j = 0; j < 4; ++j) acc2[i][j] = 0ull;

    for (int fc = 0; fc < TFv; fc += FCH) {
        // stage W chunk: straight float4 copy from pre-transposed wT (coalesced,
        // conflict-free: lane covers one 128-float row per iter)
        const float* src = wT + fc * Fv;
        #pragma unroll
        for (int i = 0; i < 8; ++i) {
            const int e = t * 4 + i * 1024;
            const float4 v = __ldg((const float4*)(src + e));
            *(float4*)&s_w[e >> 7][e & 127] = v;
        }
        __syncthreads();

        #pragma unroll 8
        for (int f = 0; f < FCH; ++f) {
            const unsigned long long a0 = pk2(s_cat[ty4 + 0][fc + f], s_cat[ty4 + 0][fc + f]);
            const unsigned long long a1 = pk2(s_cat[ty4 + 1][fc + f], s_cat[ty4 + 1][fc + f]);
            const unsigned long long a2 = pk2(s_cat[ty4 + 2][fc + f], s_cat[ty4 + 2][fc + f]);
            const unsigned long long a3 = pk2(s_cat[ty4 + 3][fc + f], s_cat[ty4 + 3][fc + f]);
            const float4 w0 = *(const float4*)&s_w[f][tx8];
            const float4 w1 = *(const float4*)&s_w[f][tx8 + 4];
            const unsigned long long wp0 = pk2(w0.x, w0.y);
            const unsigned long long wp1 = pk2(w0.z, w0.w);
            const unsigned long long wp2 = pk2(w1.x, w1.y);
            const unsigned long long wp3 = pk2(w1.z, w1.w);
            fma2(acc2[0][0], a0, wp0); fma2(acc2[0][1], a0, wp1);
            fma2(acc2[0][2], a0, wp2); fma2(acc2[0][3], a0, wp3);
            fma2(acc2[1][0], a1, wp0); fma2(acc2[1][1], a1, wp1);
            fma2(acc2[1][2], a1, wp2); fma2(acc2[1][3], a1, wp3);
            fma2(acc2[2][0], a2, wp0); fma2(acc2[2][1], a2, wp1);
            fma2(acc2[2][2], a2, wp2); fma2(acc2[2][3], a2, wp3);
            fma2(acc2[3][0], a3, wp0); fma2(acc2[3][1], a3, wp1);
            fma2(acc2[3][2], a3, wp2); fma2(acc2[3][3], a3, wp3);
        }
        __syncthreads();
    }

    // ---- Epilogue: + bias, store ----
    float bja[8];
    #pragma unroll
    for (int j = 0; j < 8; ++j) bja[j] = __ldg(bias + tx8 + j);
    #pragma unroll
    for (int i = 0; i < 4; ++i) {
        float v[8];
        #pragma unroll
        for (int j = 0; j < 4; ++j) upk2(acc2[i][j], v[2 * j], v[2 * j + 1]);
        const int rowg = row0 + ty4 + i;
        float* o = hout + rowg * Fv + tx8;
        *(float4*)o       = make_float4(v[0] + bja[0], v[1] + bja[1], v[2] + bja[2], v[3] + bja[3]);
        *(float4*)(o + 4) = make_float4(v[4] + bja[4], v[5] + bja[5], v[6] + bja[6], v[7] + bja[7]);
    }
}

// Tail part 1: z[b][j] = h[b,0,:] . l1w[j,:] + l1b[j]   (grid=B, block=64)
__global__ __launch_bounds__(64) void lin1_kernel(
    const float* __restrict__ h,
    const float* __restrict__ l1w, const float* __restrict__ l1b,
    float* __restrict__ z)
{
    const int b = blockIdx.x;
    const int j = threadIdx.x;
    const float4* hr = (const float4*)(h + b * Nv * Fv);
    const float4* wr = (const float4*)(l1w + j * Fv);
    float s = 0.f;
    #pragma unroll
    for (int q = 0; q < Fv / 4; ++q) {
        const float4 a = __ldg(hr + q);
        const float4 w = __ldg(wr + q);
        s = fmaf(a.x, w.x, s); s = fmaf(a.y, w.y, s);
        s = fmaf(a.z, w.z, s); s = fmaf(a.w, w.w, s);
    }
    z[b * 64 + j] = s + __ldg(l1b + j);
}

// Tail part 2: BN (batch stats) -> relu -> lin2 -> softmax  (1 block, 128 threads)
__global__ __launch_bounds__(128) void tail_kernel(
    const float* __restrict__ z_in,
    const float* __restrict__ gamma, const float* __restrict__ beta,
    const float* __restrict__ l2w, const float* __restrict__ l2b,
    float* __restrict__ out)
{
    __shared__ float s_z[Bv][65];
    __shared__ float s_scale[64], s_shift[64];
    const int t = threadIdx.x;

    for (int o = t; o < Bv * 64; o += 128) {
        s_z[o >> 6][o & 63] = z_in[o];
    }
    __syncthreads();

    if (t < 64) {
        float mu = 0.f;
        #pragma unroll 4
        for (int b = 0; b < Bv; ++b) mu += s_z[b][t];
        mu *= (1.0f / Bv);
        float var = 0.f;
        #pragma unroll 4
        for (int b = 0; b < Bv; ++b) { const float d = s_z[b][t] - mu; var += d * d; }
        var *= (1.0f / Bv);
        const float sc = gamma[t] * rsqrtf(var + 1e-5f);
        s_scale[t] = sc;
        s_shift[t] = beta[t] - mu * sc;
    }
    __syncthreads();

    for (int o = t; o < Bv * 64; o += 128) {
        const int b = o >> 6, j = o & 63;
        s_z[b][j] = fmaxf(s_z[b][j] * s_scale[j] + s_shift[j], 0.f);
    }
    __syncthreads();

    // lin2 + softmax, one thread per batch row
    {
        float lg[Cv];
        #pragma unroll
        for (int c = 0; c < Cv; ++c) {
            const float* wr = l2w + c * 64;
            float s = 0.f;
            #pragma unroll
            for (int j = 0; j < 64; ++j) s = fmaf(s_z[t][j], wr[j], s);
            lg[c] = s + l2b[c];
        }
        float m = lg[0];
        #pragma unroll
        for (int c = 1; c < Cv; ++c) m = fmaxf(m, lg[c]);
        float sum = 0.f;
        #pragma unroll
        for (int c = 0; c < Cv; ++c) { lg[c] = expf(lg[c] - m); sum += lg[c]; }
        const float r = 1.0f / sum;
        #pragma unroll
        for (int c = 0; c < Cv; ++c) out[t * Cv + c] = lg[c] * r;
    }
}

extern "C" void kernel_launch(void* const* d_in, const int* in_sizes, int n_in,
                              void* d_out, int out_size) {
    const float* x      = (const float*)d_in[0];
    const int*   neigh  = (const int*)  d_in[1];
    const float* w_sage = (const float*)d_in[2];
    const float* b_sage = (const float*)d_in[3];
    const float* l1w    = (const float*)d_in[4];
    const float* l1b    = (const float*)d_in[5];
    const float* gamma  = (const float*)d_in[6];
    const float* beta   = (const float*)d_in[7];
    const float* l2w    = (const float*)d_in[8];
    const float* l2b    = (const float*)d_in[9];
    float* out = (float*)d_out;

    cudaFuncSetAttribute(sage_layer_kernel,
                         cudaFuncAttributeMaxDynamicSharedMemorySize, SMEM_BYTES);

    void *p1, *p2, *pw, *pz;
    cudaGetSymbolAddress(&p1, g_h1);
    cudaGetSymbolAddress(&p2, g_h2);
    cudaGetSymbolAddress(&pw, g_wT);
    cudaGetSymbolAddress(&pz, g_z);
    float* h1 = (float*)p1;
    float* h2 = (float*)p2;
    float* wT = (float*)pw;
    float* z  = (float*)pz;

    transpose_w_kernel<<<256, 256>>>(w_sage, wT);

    const int grid = (Bv * Nv) / ROWS;  // 1024
    sage_layer_kernel<<<grid, THREADS, SMEM_BYTES>>>(x,  neigh, wT,              b_sage,      h1);
    sage_layer_kernel<<<grid, THREADS, SMEM_BYTES>>>(h1, neigh, wT + TFv * Fv,   b_sage + Fv, h2);

    lin1_kernel<<<Bv, 64>>>(h2, l1w, l1b, z);
    tail_kernel<<<1, 128>>>(z, gamma, beta, l2w, l2b, out);
}

// round 4
// speedup vs baseline: 5.6448x; 2.1974x over previous
#include <cuda_runtime.h>
#include <cuda_bf16.h>
#include <math.h>
#include <stdint.h>

// Problem constants
constexpr int Bv = 128, Nv = 512, Kv = 10, Fv = 128, TFv = 256, Cv = 40;

// Layer tiling
constexpr int MT      = 64;     // rows per CTA
constexpr int THREADS = 256;
constexpr int PITCH   = 136;    // bf16 elems per row (128 + 8 pad = 272 B)
constexpr int A_BYTES = MT * PITCH * 2;    // 17408
constexpr int W_BYTES = 128 * PITCH * 2;   // 34816
constexpr int A_HI = 0;
constexpr int A_LO = A_HI + A_BYTES;       // 17408
constexpr int W_HI = A_LO + A_BYTES;       // 34816
constexpr int W_LO = W_HI + W_BYTES;       // 69632
constexpr int SMEM_BYTES = W_LO + W_BYTES; // 104448

// Scratch (static device globals: allocation-free rule)
__device__ float g_h1[Bv * Nv * Fv];
__device__ float g_h2[Bv * Nv * Fv];
// Pre-split padded weights: [layer][kchunk][part hi/lo][128][PITCH] bf16
__device__ __nv_bfloat16 g_wp[2][2][2][128][PITCH];
__device__ float g_z[Bv * 64];

// ---------------- bf16 HMMA (sm_80+ base feature; no 'a' target needed) ----------------
__device__ __forceinline__ void mma_bf16(float* c, const uint32_t* a,
                                         uint32_t b0, uint32_t b1) {
    asm volatile(
        "mma.sync.aligned.m16n8k16.row.col.f32.bf16.bf16.f32 "
        "{%0,%1,%2,%3}, {%4,%5,%6,%7}, {%8,%9}, {%0,%1,%2,%3};"
        : "+f"(c[0]), "+f"(c[1]), "+f"(c[2]), "+f"(c[3])
        : "r"(a[0]), "r"(a[1]), "r"(a[2]), "r"(a[3]), "r"(b0), "r"(b1));
}

// ---------------- prep: split + pad weights ----------------
__global__ __launch_bounds__(256) void prep_w_kernel(const float* __restrict__ w) {
    const int idx = blockIdx.x * 256 + threadIdx.x;  // 2*128*256 = 65536
    const int l = idx >> 15;
    const int r = idx & 32767;
    const int g = r >> 8;       // output row (0..127)
    const int k = r & 255;      // input col
    const float v = w[l * (TFv * Fv) + g * TFv + k];
    const __nv_bfloat16 hi = __float2bfloat16(v);
    const __nv_bfloat16 lo = __float2bfloat16(v - __bfloat162float(hi));
    const int chunk = k >> 7, kk = k & 127;
    g_wp[l][chunk][0][g][kk] = hi;
    g_wp[l][chunk][1][g][kk] = lo;
}

// split a float4 into bf16 hi/lo packed pairs
__device__ __forceinline__ void split4(const float4 v, uint2& hi, uint2& lo) {
    __nv_bfloat16 h[4], l[4];
    const float va[4] = {v.x, v.y, v.z, v.w};
    #pragma unroll
    for (int q = 0; q < 4; ++q) {
        h[q] = __float2bfloat16(va[q]);
        l[q] = __float2bfloat16(va[q] - __bfloat162float(h[q]));
    }
    hi = *(uint2*)h;
    lo = *(uint2*)l;
}

// ---------------- fused SAGE layer: gather-mean + bf16x3 HMMA GEMM ----------------
__global__ __launch_bounds__(THREADS, 2) void sage_layer_mma(
    const float* __restrict__ hin, const int* __restrict__ neigh,
    const __nv_bfloat16* __restrict__ wp,   // -> g_wp[layer]
    const float* __restrict__ bias, float* __restrict__ hout)
{
    extern __shared__ char sm[];
    const int t = threadIdx.x, lane = t & 31, warp = t >> 5;
    const int row0 = blockIdx.x * MT;

    const int wm = (warp >> 1) * 16;      // warp row offset: 0,16,32,48
    const int wn = (warp & 1) * 64;       // warp col offset: 0,64
    const int qr = lane >> 2;             // 0-7
    const int qc = (lane & 3) * 2;        // 0,2,4,6

    float acc[8][4];
    #pragma unroll
    for (int nt = 0; nt < 8; ++nt)
        #pragma unroll
        for (int q = 0; q < 4; ++q) acc[nt][q] = 0.f;

    #pragma unroll
    for (int phase = 0; phase < 2; ++phase) {
        // ---- Stage A: phase 0 = gather-mean, phase 1 = self features ----
        #pragma unroll
        for (int i = 0; i < 2; ++i) {
            const int r    = warp * 8 + (lane >> 4) * 4 + i * 2 + ((lane >> 3) & 1);
            // 8 rows per warp: split 32 lanes as 16 lanes per row is awkward; use
            // simple mapping instead: each warp does rows warp*8 .. +8 serially.
            (void)r;
        }
        for (int r = warp * 8; r < warp * 8 + 8; ++r) {
            const int rowg = row0 + r;
            const int b    = rowg >> 9;            // N = 512
            float4 val;
            if (phase == 0) {
                const int* nb = neigh + rowg * Kv;
                float4 a4 = make_float4(0.f, 0.f, 0.f, 0.f);
                #pragma unroll
                for (int k = 0; k < Kv; ++k) {
                    const int idx = __ldg(nb + k);
                    const float4 v = __ldg((const float4*)(hin + (b * Nv + idx) * Fv) + lane);
                    a4.x += v.x; a4.y += v.y; a4.z += v.z; a4.w += v.w;
                }
                const float inv = 1.0f / Kv;
                val = make_float4(a4.x * inv, a4.y * inv, a4.z * inv, a4.w * inv);
            } else {
                val = __ldg((const float4*)(hin + rowg * Fv) + lane);
            }
            uint2 hi, lo;
            split4(val, hi, lo);
            const int off = r * (PITCH * 2) + lane * 8;
            *(uint2*)(sm + A_HI + off) = hi;
            *(uint2*)(sm + A_LO + off) = lo;
        }

        // ---- Stage W chunk (hi+lo contiguous 69632 B, already final layout) ----
        {
            const uint4* src = (const uint4*)(wp + (size_t)phase * 2 * 128 * PITCH);
            uint4* dst = (uint4*)(sm + W_HI);
            #pragma unroll
            for (int i = 0; i < 17; ++i)
                dst[t + i * 256] = __ldg(src + t + i * 256);
        }
        __syncthreads();

        // ---- MMA: 8 k-steps of m16n8k16, 3 split products each ----
        #pragma unroll
        for (int ks = 0; ks < 8; ++ks) {
            const int k = ks * 16;
            uint32_t ah[4], al[4];
            {
                const int r0 = (wm + qr) * (PITCH * 2);
                const int r8 = (wm + qr + 8) * (PITCH * 2);
                const int c0 = (k + qc) * 2, c8 = (k + qc + 8) * 2;
                ah[0] = *(const uint32_t*)(sm + A_HI + r0 + c0);
                ah[1] = *(const uint32_t*)(sm + A_HI + r8 + c0);
                ah[2] = *(const uint32_t*)(sm + A_HI + r0 + c8);
                ah[3] = *(const uint32_t*)(sm + A_HI + r8 + c8);
                al[0] = *(const uint32_t*)(sm + A_LO + r0 + c0);
                al[1] = *(const uint32_t*)(sm + A_LO + r8 + c0);
                al[2] = *(const uint32_t*)(sm + A_LO + r0 + c8);
                al[3] = *(const uint32_t*)(sm + A_LO + r8 + c8);
            }
            #pragma unroll
            for (int nt = 0; nt < 8; ++nt) {
                const int n  = wn + nt * 8 + qr;
                const int rb = n * (PITCH * 2);
                const int c0 = (k + qc) * 2, c8 = (k + qc + 8) * 2;
                const uint32_t bh0 = *(const uint32_t*)(sm + W_HI + rb + c0);
                const uint32_t bh1 = *(const uint32_t*)(sm + W_HI + rb + c8);
                const uint32_t bl0 = *(const uint32_t*)(sm + W_LO + rb + c0);
                const uint32_t bl1 = *(const uint32_t*)(sm + W_LO + rb + c8);
                mma_bf16(acc[nt], ah, bh0, bh1);
                mma_bf16(acc[nt], al, bh0, bh1);
                mma_bf16(acc[nt], ah, bl0, bl1);
            }
        }
        __syncthreads();   // A/W buffers reused next phase
    }

    // ---- Epilogue: + bias, store fragments ----
    #pragma unroll
    for (int nt = 0; nt < 8; ++nt) {
        const int col = wn + nt * 8 + qc;
        const float b0 = __ldg(bias + col);
        const float b1 = __ldg(bias + col + 1);
        const int rA = row0 + wm + qr;
        float2 o0 = make_float2(acc[nt][0] + b0, acc[nt][1] + b1);
        float2 o1 = make_float2(acc[nt][2] + b0, acc[nt][3] + b1);
        *(float2*)(hout + rA * Fv + col) = o0;
        *(float2*)(hout + (rA + 8) * Fv + col) = o1;
    }
}

// ---------------- tail part 1: z = h[:,0,:] @ l1w^T + l1b ----------------
__global__ __launch_bounds__(256) void lin1_kernel(
    const float* __restrict__ h,
    const float* __restrict__ l1w, const float* __restrict__ l1b,
    float* __restrict__ z)
{
    __shared__ float red[4][64];
    const int b  = blockIdx.x;
    const int j  = threadIdx.x & 63;
    const int sl = threadIdx.x >> 6;
    const float4* hr = (const float4*)(h + b * Nv * Fv) + sl * 8;
    const float4* wr = (const float4*)(l1w + j * Fv) + sl * 8;
    float s = 0.f;
    #pragma unroll
    for (int q = 0; q < 8; ++q) {
        const float4 a = __ldg(hr + q);
        const float4 w = __ldg(wr + q);
        s = fmaf(a.x, w.x, s); s = fmaf(a.y, w.y, s);
        s = fmaf(a.z, w.z, s); s = fmaf(a.w, w.w, s);
    }
    red[sl][j] = s;
    __syncthreads();
    if (sl == 0)
        z[b * 64 + j] = red[0][j] + red[1][j] + red[2][j] + red[3][j] + __ldg(l1b + j);
}

// ---------------- tail part 2: BN -> relu -> lin2 -> softmax ----------------
__global__ __launch_bounds__(128) void tail_kernel(
    const float* __restrict__ z_in,
    const float* __restrict__ gamma, const float* __restrict__ beta,
    const float* __restrict__ l2w, const float* __restrict__ l2b,
    float* __restrict__ out)
{
    __shared__ float s_z[Bv][65];
    __shared__ float s_scale[64], s_shift[64];
    const int t = threadIdx.x;

    for (int o = t; o < Bv * 64; o += 128) s_z[o >> 6][o & 63] = z_in[o];
    __syncthreads();

    if (t < 64) {
        float mu = 0.f;
        #pragma unroll 4
        for (int b = 0; b < Bv; ++b) mu += s_z[b][t];
        mu *= (1.0f / Bv);
        float var = 0.f;
        #pragma unroll 4
        for (int b = 0; b < Bv; ++b) { const float d = s_z[b][t] - mu; var += d * d; }
        var *= (1.0f / Bv);
        const float sc = gamma[t] * rsqrtf(var + 1e-5f);
        s_scale[t] = sc;
        s_shift[t] = beta[t] - mu * sc;
    }
    __syncthreads();

    for (int o = t; o < Bv * 64; o += 128) {
        const int b = o >> 6, j = o & 63;
        s_z[b][j] = fmaxf(s_z[b][j] * s_scale[j] + s_shift[j], 0.f);
    }
    __syncthreads();

    {
        float lg[Cv];
        #pragma unroll
        for (int c = 0; c < Cv; ++c) {
            const float* wr = l2w + c * 64;
            float s = 0.f;
            #pragma unroll
            for (int j = 0; j < 64; ++j) s = fmaf(s_z[t][j], wr[j], s);
            lg[c] = s + l2b[c];
        }
        float m = lg[0];
        #pragma unroll
        for (int c = 1; c < Cv; ++c) m = fmaxf(m, lg[c]);
        float sum = 0.f;
        #pragma unroll
        for (int c = 0; c < Cv; ++c) { lg[c] = expf(lg[c] - m); sum += lg[c]; }
        const float r = 1.0f / sum;
        #pragma unroll
        for (int c = 0; c < Cv; ++c) out[t * Cv + c] = lg[c] * r;
    }
}

extern "C" void kernel_launch(void* const* d_in, const int* in_sizes, int n_in,
                              void* d_out, int out_size) {
    const float* x      = (const float*)d_in[0];
    const int*   neigh  = (const int*)  d_in[1];
    const float* w_sage = (const float*)d_in[2];
    const float* b_sage = (const float*)d_in[3];
    const float* l1w    = (const float*)d_in[4];
    const float* l1b    = (const float*)d_in[5];
    const float* gamma  = (const float*)d_in[6];
    const float* beta   = (const float*)d_in[7];
    const float* l2w    = (const float*)d_in[8];
    const float* l2b    = (const float*)d_in[9];
    float* out = (float*)d_out;

    cudaFuncSetAttribute(sage_layer_mma,
                         cudaFuncAttributeMaxDynamicSharedMemorySize, SMEM_BYTES);

    void *p1, *p2, *pw, *pz;
    cudaGetSymbolAddress(&p1, g_h1);
    cudaGetSymbolAddress(&p2, g_h2);
    cudaGetSymbolAddress(&pw, g_wp);
    cudaGetSymbolAddress(&pz, g_z);
    float* h1 = (float*)p1;
    float* h2 = (float*)p2;
    __nv_bfloat16* wb = (__nv_bfloat16*)pw;
    float* z = (float*)pz;

    prep_w_kernel<<<256, 256>>>(w_sage);

    const int grid = (Bv * Nv) / MT;  // 1024
    const int wlayer = 2 * 2 * 128 * PITCH;  // elems per layer in g_wp
    sage_layer_mma<<<grid, THREADS, SMEM_BYTES>>>(x,  neigh, wb,          b_sage,      h1);
    sage_layer_mma<<<grid, THREADS, SMEM_BYTES>>>(h1, neigh, wb + wlayer, b_sage + Fv, h2);

    lin1_kernel<<<Bv, 256>>>(h2, l1w, l1b, z);
    tail_kernel<<<1, 128>>>(z, gamma, beta, l2w, l2b, out);
}